// round 10
// baseline (speedup 1.0000x reference)
#include <cuda_runtime.h>
#include <math.h>
#include <stdint.h>

#define BB 4
#define SS 4096
#define DD 256
#define HH 4
#define HD 64
#define NN (BB*SS)
#define INV_TEMP 0.125f
#define LN_EPS 1e-5f

typedef unsigned long long ull;

// Scratch (allocation-free): 8 x 16 MiB device globals.
__device__ float g_xn[NN*DD];
__device__ float g_q[NN*DD];
__device__ float g_k[NN*DD];
__device__ float g_v[NN*DD];
__device__ float g_att[NN*DD];
__device__ float g_xt[NN*DD];
__device__ float g_h[NN*DD];
__device__ float g_a1[NN*DD];

// ---- packed f32x2 helpers ----
__device__ __forceinline__ ull ffma2(ull a, ull b, ull c) {
    ull d; asm("fma.rn.f32x2 %0, %1, %2, %3;" : "=l"(d) : "l"(a), "l"(b), "l"(c)); return d;
}
__device__ __forceinline__ ull fmul2(ull a, ull b) {
    ull d; asm("mul.rn.f32x2 %0, %1, %2;" : "=l"(d) : "l"(a), "l"(b)); return d;
}
__device__ __forceinline__ ull pack2(float lo, float hi) {
    ull d; asm("mov.b64 %0, {%1, %2};" : "=l"(d) : "f"(lo), "f"(hi)); return d;
}
__device__ __forceinline__ void unpack2(ull v, float& lo, float& hi) {
    asm("mov.b64 {%0, %1}, %2;" : "=f"(lo), "=f"(hi) : "l"(v));
}
__device__ __forceinline__ float hsum2(ull v) {
    float lo, hi; unpack2(v, lo, hi); return lo + hi;
}

// ---- cp.async ----
__device__ __forceinline__ uint32_t smem_u32(const void* p) {
    uint32_t a;
    asm("{ .reg .u64 t; cvta.to.shared.u64 t, %1; cvt.u32.u64 %0, t; }" : "=r"(a) : "l"(p));
    return a;
}
__device__ __forceinline__ void cp_async16(uint32_t saddr, const void* g) {
    asm volatile("cp.async.cg.shared.global [%0], [%1], 16;" :: "r"(saddr), "l"(g));
}
#define CP_COMMIT() asm volatile("cp.async.commit_group;" ::: "memory")
#define CP_WAIT0()  asm volatile("cp.async.wait_group 0;" ::: "memory")

__device__ __forceinline__ float warp_sum(float v) {
    #pragma unroll
    for (int o = 16; o; o >>= 1) v += __shfl_xor_sync(0xffffffffu, v, o);
    return v;
}

// LayerNorm (optionally fused residual add). One block per row, 256 threads.
__global__ void ln_kernel(const float* __restrict__ x, const float* __restrict__ res,
                          const float* __restrict__ g, const float* __restrict__ b,
                          float* __restrict__ xt_out, float* __restrict__ y) {
    int row = blockIdx.x;
    int t = threadIdx.x;
    size_t i = (size_t)row * DD + t;
    float v = x[i];
    if (res) v += res[i];
    if (xt_out) xt_out[i] = v;

    __shared__ float red1[8], red2[8];
    float s1 = warp_sum(v);
    float s2 = warp_sum(v * v);
    if ((t & 31) == 0) { red1[t >> 5] = s1; red2[t >> 5] = s2; }
    __syncthreads();
    float tot = 0.f, tot2 = 0.f;
    #pragma unroll
    for (int w = 0; w < 8; w++) { tot += red1[w]; tot2 += red2[w]; }
    float mu = tot * (1.f / DD);
    float var = tot2 * (1.f / DD) - mu * mu;
    float rstd = rsqrtf(var + LN_EPS);
    y[i] = (v - mu) * rstd * g[t] + b[t];
}

// C[M,256] = A[M,256] @ W[256,256]^T. NT GEMM, FFMA2 k-packed, 8x8 micro-tile.
// BM=64, BN=128, BK=16; 128 threads; rows tr+i (tr=(tid/16)*8), cols tc+16*j.
// epi: 0 = plain; 1 = +bias,relu; 2 = +bias +res
#define GS 18
__global__ void __launch_bounds__(128, 2) gemm_nt(
        const float* __restrict__ A, const float* __restrict__ W,
        const float* __restrict__ bias, const float* __restrict__ res,
        float* __restrict__ C, int epi) {
    __shared__ float As[64 * GS];
    __shared__ float Bs[128 * GS];
    int tid = threadIdx.x;
    int bm = blockIdx.y * 64, bn = blockIdx.x * 128;
    int tr = (tid >> 4) * 8;      // 0..56
    int tc = tid & 15;            // 0..15

    int am[2], ak[2], wn[4], wk[4];
    #pragma unroll
    for (int p = 0; p < 2; p++) { int idx = tid + p * 128; am[p] = idx >> 2; ak[p] = (idx & 3) * 4; }
    #pragma unroll
    for (int p = 0; p < 4; p++) { int idx = tid + p * 128; wn[p] = idx >> 2; wk[p] = (idx & 3) * 4; }

    ull acc2[8][8];
    #pragma unroll
    for (int i = 0; i < 8; i++)
        #pragma unroll
        for (int j = 0; j < 8; j++) acc2[i][j] = 0ull;

    float4 pa[2], pb[4];
    #pragma unroll
    for (int p = 0; p < 2; p++) pa[p] = *(const float4*)&A[(size_t)(bm + am[p]) * DD + ak[p]];
    #pragma unroll
    for (int p = 0; p < 4; p++) pb[p] = *(const float4*)&W[(size_t)(bn + wn[p]) * DD + wk[p]];

    for (int k0 = 0; k0 < DD; k0 += 16) {
        #pragma unroll
        for (int p = 0; p < 2; p++) {
            As[am[p] * GS + ak[p] + 0] = pa[p].x; As[am[p] * GS + ak[p] + 1] = pa[p].y;
            As[am[p] * GS + ak[p] + 2] = pa[p].z; As[am[p] * GS + ak[p] + 3] = pa[p].w;
        }
        #pragma unroll
        for (int p = 0; p < 4; p++) {
            Bs[wn[p] * GS + wk[p] + 0] = pb[p].x; Bs[wn[p] * GS + wk[p] + 1] = pb[p].y;
            Bs[wn[p] * GS + wk[p] + 2] = pb[p].z; Bs[wn[p] * GS + wk[p] + 3] = pb[p].w;
        }
        __syncthreads();

        if (k0 + 16 < DD) {
            #pragma unroll
            for (int p = 0; p < 2; p++) pa[p] = *(const float4*)&A[(size_t)(bm + am[p]) * DD + k0 + 16 + ak[p]];
            #pragma unroll
            for (int p = 0; p < 4; p++) pb[p] = *(const float4*)&W[(size_t)(bn + wn[p]) * DD + k0 + 16 + wk[p]];
        }

        #pragma unroll
        for (int kk = 0; kk < 16; kk += 2) {
            ull a2[8], b2[8];
            #pragma unroll
            for (int i = 0; i < 8; i++) a2[i] = *(const ull*)&As[(tr + i) * GS + kk];
            #pragma unroll
            for (int j = 0; j < 8; j++) b2[j] = *(const ull*)&Bs[(tc + 16 * j) * GS + kk];
            #pragma unroll
            for (int i = 0; i < 8; i++)
                #pragma unroll
                for (int j = 0; j < 8; j++) acc2[i][j] = ffma2(a2[i], b2[j], acc2[i][j]);
        }
        __syncthreads();
    }

    #pragma unroll
    for (int i = 0; i < 8; i++) {
        int m = bm + tr + i;
        #pragma unroll
        for (int j = 0; j < 8; j++) {
            int n = bn + tc + 16 * j;
            float v = hsum2(acc2[i][j]);
            if (epi >= 1) v += bias[n];
            if (epi == 1) v = fmaxf(v, 0.f);
            if (epi == 2) v += res[(size_t)m * DD + n];
            C[(size_t)m * DD + n] = v;
        }
    }
}

// Flash attention, causal. 128-row q-tile x 128-col kv-tiles. 256 threads.
// 8x8 score micro-tile (s2 packed over d), 8x4 PV micro-tile.
// Q/K/V tiles: stride SP=68 (64 cols + pad). P tile: stride PS=132 (128 cols + pad).
#define SP 68
#define PS 132
#define ATILF (128 * SP)             // 8704 floats per Q/K/V tile
#define PTILF (128 * PS)             // 16896 floats for P
#define SMEM_ATTN ((3 * ATILF + PTILF) * 4)   // 168 KB
__global__ void __launch_bounds__(256, 1) attn_kernel(
        const float* __restrict__ q, const float* __restrict__ k,
        const float* __restrict__ v, float* __restrict__ att) {
    extern __shared__ float sm[];
    float* Qs = sm;
    float* Ks = sm + ATILF;
    float* Vs = sm + 2 * ATILF;
    float* Ps = sm + 3 * ATILF;
    uint32_t sbase = smem_u32(sm);

    int bh = blockIdx.y;
    int b = bh >> 2, h = bh & 3;
    int qt = 31 - blockIdx.x;      // longest blocks launch first
    int tid = threadIdx.x;
    int ty = tid >> 4;
    int tx = tid & 15;

    const float* qbase = q + (size_t)b * SS * DD + h * HD;
    const float* kbase = k + (size_t)b * SS * DD + h * HD;
    const float* vbase = v + (size_t)b * SS * DD + h * HD;

    // Load Q tile (scaled): 128 rows x 64 = 2048 float4, 8 per thread.
    #pragma unroll
    for (int it = 0; it < 8; it++) {
        int l = tid + it * 256;
        int rr = l >> 4, d4 = (l & 15) * 4;
        float4 tv = *(const float4*)&qbase[(size_t)(qt * 128 + rr) * DD + d4];
        Qs[rr * SP + d4 + 0] = tv.x * INV_TEMP;
        Qs[rr * SP + d4 + 1] = tv.y * INV_TEMP;
        Qs[rr * SP + d4 + 2] = tv.z * INV_TEMP;
        Qs[rr * SP + d4 + 3] = tv.w * INV_TEMP;
    }

    ull acc2[8][2];
    float m_i[8], l_i[8];
    #pragma unroll
    for (int rr = 0; rr < 8; rr++) {
        m_i[rr] = -INFINITY; l_i[rr] = 0.f;
        acc2[rr][0] = 0ull; acc2[rr][1] = 0ull;
    }

    for (int kt = 0; kt <= qt; kt++) {
        // Fill K,V (single buffer; prior tile consumption guarded by loop-end barrier)
        #pragma unroll
        for (int it = 0; it < 8; it++) {
            int l = tid + it * 256;
            int rr = l >> 4, d4 = (l & 15) * 4;
            size_t gofs = ((size_t)(kt * 128 + rr) * DD + d4) * 4;
            uint32_t sofs = (uint32_t)(rr * SP + d4) * 4;
            cp_async16(sbase + ATILF * 4 + sofs, (const char*)kbase + gofs);
            cp_async16(sbase + 2 * ATILF * 4 + sofs, (const char*)vbase + gofs);
        }
        CP_COMMIT();
        CP_WAIT0();
        __syncthreads();

        // Scores: s2[rr][c] packed over d-pairs; kp loaded inside c-loop (reg pressure)
        ull s2[8][8];
        #pragma unroll
        for (int rr = 0; rr < 8; rr++)
            #pragma unroll
            for (int c = 0; c < 8; c++) s2[rr][c] = 0ull;

        #pragma unroll 4
        for (int d0 = 0; d0 < 64; d0 += 4) {
            ulonglong2 qp[8];
            #pragma unroll
            for (int rr = 0; rr < 8; rr++)
                qp[rr] = *(const ulonglong2*)&Qs[(ty * 8 + rr) * SP + d0];
            #pragma unroll
            for (int c = 0; c < 8; c++) {
                ulonglong2 kp = *(const ulonglong2*)&Ks[(tx + 16 * c) * SP + d0];
                #pragma unroll
                for (int rr = 0; rr < 8; rr++) {
                    s2[rr][c] = ffma2(qp[rr].x, kp.x, s2[rr][c]);
                    s2[rr][c] = ffma2(qp[rr].y, kp.y, s2[rr][c]);
                }
            }
        }

        bool diag = (kt == qt);
        #pragma unroll
        for (int rr = 0; rr < 8; rr++) {
            int row = ty * 8 + rr;
            float sv[8];
            float mx = -INFINITY;
            #pragma unroll
            for (int c = 0; c < 8; c++) {
                sv[c] = hsum2(s2[rr][c]);
                int j = tx + 16 * c;
                if (diag && j > row) sv[c] = -INFINITY;
                mx = fmaxf(mx, sv[c]);
            }
            mx = fmaxf(mx, __shfl_xor_sync(0xffffffffu, mx, 1));
            mx = fmaxf(mx, __shfl_xor_sync(0xffffffffu, mx, 2));
            mx = fmaxf(mx, __shfl_xor_sync(0xffffffffu, mx, 4));
            mx = fmaxf(mx, __shfl_xor_sync(0xffffffffu, mx, 8));
            float m_new = fmaxf(m_i[rr], mx);
            float alpha = __expf(m_i[rr] - m_new);

            float lsum = 0.f;
            #pragma unroll
            for (int c = 0; c < 8; c++) {
                float p = __expf(sv[c] - m_new);
                lsum += p;
                Ps[row * PS + tx + 16 * c] = p;
            }
            lsum += __shfl_xor_sync(0xffffffffu, lsum, 1);
            lsum += __shfl_xor_sync(0xffffffffu, lsum, 2);
            lsum += __shfl_xor_sync(0xffffffffu, lsum, 4);
            lsum += __shfl_xor_sync(0xffffffffu, lsum, 8);
            l_i[rr] = l_i[rr] * alpha + lsum;
            m_i[rr] = m_new;
            ull al2 = pack2(alpha, alpha);
            acc2[rr][0] = fmul2(acc2[rr][0], al2);
            acc2[rr][1] = fmul2(acc2[rr][1], al2);
        }

        // P rows for this thread's ty are produced & consumed within the same warp.
        __syncwarp();

        // PV: acc2[rr][h2] += sum_j P[ty*8+rr][j] * V[j][tx*4 + 2*h2 ..]
        #pragma unroll 8
        for (int j0 = 0; j0 < 128; j0 += 4) {
            float4 pv[8];
            ulonglong2 vv[4];
            #pragma unroll
            for (int jj = 0; jj < 4; jj++)
                vv[jj] = *(const ulonglong2*)&Vs[(j0 + jj) * SP + tx * 4];
            #pragma unroll
            for (int rr = 0; rr < 8; rr++)
                pv[rr] = *(const float4*)&Ps[(ty * 8 + rr) * PS + j0];
            #pragma unroll
            for (int rr = 0; rr < 8; rr++) {
                const float* pr = &pv[rr].x;
                #pragma unroll
                for (int jj = 0; jj < 4; jj++) {
                    ull pb = pack2(pr[jj], pr[jj]);
                    acc2[rr][0] = ffma2(pb, vv[jj].x, acc2[rr][0]);
                    acc2[rr][1] = ffma2(pb, vv[jj].y, acc2[rr][1]);
                }
            }
        }
        __syncthreads();   // all reads of K,V,P done before next fill
    }

    float* obase = att + (size_t)b * SS * DD + h * HD;
    #pragma unroll
    for (int rr = 0; rr < 8; rr++) {
        float inv = 1.f / l_i[rr];
        size_t orow = (size_t)(qt * 128 + ty * 8 + rr) * DD + tx * 4;
        float a0, a1, a2, a3;
        unpack2(acc2[rr][0], a0, a1);
        unpack2(acc2[rr][1], a2, a3);
        float4 o = make_float4(a0 * inv, a1 * inv, a2 * inv, a3 * inv);
        *(float4*)&obase[orow] = o;
    }
}

extern "C" void kernel_launch(void* const* d_in, const int* in_sizes, int n_in,
                              void* d_out, int out_size) {
    const float* x   = (const float*)d_in[0];
    const float* Wq  = (const float*)d_in[1];
    const float* Wk  = (const float*)d_in[2];
    const float* Wv  = (const float*)d_in[3];
    const float* g1  = (const float*)d_in[4];
    const float* b1  = (const float*)d_in[5];
    const float* g2  = (const float*)d_in[6];
    const float* b2  = (const float*)d_in[7];
    const float* W1  = (const float*)d_in[8];
    const float* bf1 = (const float*)d_in[9];
    const float* W2  = (const float*)d_in[10];
    const float* bf2 = (const float*)d_in[11];
    float* out = (float*)d_out;

    float *xn, *q, *k, *v, *att, *xt, *h, *a1;
    cudaGetSymbolAddress((void**)&xn,  g_xn);
    cudaGetSymbolAddress((void**)&q,   g_q);
    cudaGetSymbolAddress((void**)&k,   g_k);
    cudaGetSymbolAddress((void**)&v,   g_v);
    cudaGetSymbolAddress((void**)&att, g_att);
    cudaGetSymbolAddress((void**)&xt,  g_xt);
    cudaGetSymbolAddress((void**)&h,   g_h);
    cudaGetSymbolAddress((void**)&a1,  g_a1);

    cudaFuncSetAttribute(attn_kernel, cudaFuncAttributeMaxDynamicSharedMemorySize, SMEM_ATTN);

    dim3 ggrid(DD / 128, NN / 64);   // (2, 256), 128 threads

    // 1. xn = LN(x)
    ln_kernel<<<NN, 256>>>(x, nullptr, g1, b1, nullptr, xn);
    // 2. QKV projections
    gemm_nt<<<ggrid, 128>>>(xn, Wq, nullptr, nullptr, q, 0);
    gemm_nt<<<ggrid, 128>>>(xn, Wk, nullptr, nullptr, k, 0);
    gemm_nt<<<ggrid, 128>>>(xn, Wv, nullptr, nullptr, v, 0);
    // 3. causal flash attention (128-row q-tiles)
    attn_kernel<<<dim3(SS / 128, BB * HH), 256, SMEM_ATTN>>>(q, k, v, att);
    // 4. xt = x + att; h = LN(xt)
    ln_kernel<<<NN, 256>>>(x, att, g2, b2, xt, h);
    // 5. a1 = relu(h @ W1^T + bf1)
    gemm_nt<<<ggrid, 128>>>(h, W1, bf1, nullptr, a1, 1);
    // 6. out = xt + a1 @ W2^T + bf2
    gemm_nt<<<ggrid, 128>>>(a1, W2, bf2, xt, out, 2);
}

// round 11
// speedup vs baseline: 2.0693x; 2.0693x over previous
#include <cuda_runtime.h>
#include <cuda_bf16.h>
#include <math.h>
#include <stdint.h>

#define BB 4
#define SS 4096
#define DD 256
#define HH 4
#define HD 64
#define NN (BB*SS)
#define LN_EPS 1e-5f

typedef unsigned long long ull;

// Scratch (allocation-free): 8 x 16 MiB device globals.
__device__ float g_xn[NN*DD];
__device__ float g_q[NN*DD];
__device__ float g_k[NN*DD];
__device__ float g_v[NN*DD];
__device__ float g_att[NN*DD];
__device__ float g_xt[NN*DD];
__device__ float g_h[NN*DD];
__device__ float g_a1[NN*DD];

// ---- packed f32x2 (for GEMM) ----
__device__ __forceinline__ ull ffma2(ull a, ull b, ull c) {
    ull d; asm("fma.rn.f32x2 %0, %1, %2, %3;" : "=l"(d) : "l"(a), "l"(b), "l"(c)); return d;
}
__device__ __forceinline__ void unpack2(ull v, float& lo, float& hi) {
    asm("mov.b64 {%0, %1}, %2;" : "=f"(lo), "=f"(hi) : "l"(v));
}
__device__ __forceinline__ float hsum2(ull v) {
    float lo, hi; unpack2(v, lo, hi); return lo + hi;
}

__device__ __forceinline__ uint32_t smem_u32(const void* p) {
    uint32_t a;
    asm("{ .reg .u64 t; cvta.to.shared.u64 t, %1; cvt.u32.u64 %0, t; }" : "=r"(a) : "l"(p));
    return a;
}

// ---- mma.sync / ldmatrix (base sm_80 ISA, valid on compute_103) ----
__device__ __forceinline__ void ldmx4(uint32_t* r, uint32_t a) {
    asm volatile("ldmatrix.sync.aligned.m8n8.x4.shared.b16 {%0,%1,%2,%3}, [%4];"
        : "=r"(r[0]), "=r"(r[1]), "=r"(r[2]), "=r"(r[3]) : "r"(a));
}
__device__ __forceinline__ void ldmx4t(uint32_t* r, uint32_t a) {
    asm volatile("ldmatrix.sync.aligned.m8n8.x4.trans.shared.b16 {%0,%1,%2,%3}, [%4];"
        : "=r"(r[0]), "=r"(r[1]), "=r"(r[2]), "=r"(r[3]) : "r"(a));
}
__device__ __forceinline__ void mma_bf16(float* c, const uint32_t* a, const uint32_t* b) {
    asm volatile("mma.sync.aligned.m16n8k16.row.col.f32.bf16.bf16.f32 "
        "{%0,%1,%2,%3}, {%4,%5,%6,%7}, {%8,%9}, {%0,%1,%2,%3};"
        : "+f"(c[0]), "+f"(c[1]), "+f"(c[2]), "+f"(c[3])
        : "r"(a[0]), "r"(a[1]), "r"(a[2]), "r"(a[3]), "r"(b[0]), "r"(b[1]));
}

// hi/lo bf16 split of an fp32 pair (packed bf16x2: e0 in low half).
__device__ __forceinline__ void split2(float e0, float e1, uint32_t& h, uint32_t& l) {
    __nv_bfloat162 hb = __floats2bfloat162_rn(e0, e1);
    h = reinterpret_cast<uint32_t&>(hb);
    float f0 = __bfloat162float(hb.x);
    float f1 = __bfloat162float(hb.y);
    __nv_bfloat162 lb = __floats2bfloat162_rn(e0 - f0, e1 - f1);
    l = reinterpret_cast<uint32_t&>(lb);
}

__device__ __forceinline__ float warp_sum(float v) {
    #pragma unroll
    for (int o = 16; o; o >>= 1) v += __shfl_xor_sync(0xffffffffu, v, o);
    return v;
}

// LayerNorm (optionally fused residual add). One block per row, 256 threads.
__global__ void ln_kernel(const float* __restrict__ x, const float* __restrict__ res,
                          const float* __restrict__ g, const float* __restrict__ b,
                          float* __restrict__ xt_out, float* __restrict__ y) {
    int row = blockIdx.x;
    int t = threadIdx.x;
    size_t i = (size_t)row * DD + t;
    float v = x[i];
    if (res) v += res[i];
    if (xt_out) xt_out[i] = v;

    __shared__ float red1[8], red2[8];
    float s1 = warp_sum(v);
    float s2 = warp_sum(v * v);
    if ((t & 31) == 0) { red1[t >> 5] = s1; red2[t >> 5] = s2; }
    __syncthreads();
    float tot = 0.f, tot2 = 0.f;
    #pragma unroll
    for (int w = 0; w < 8; w++) { tot += red1[w]; tot2 += red2[w]; }
    float mu = tot * (1.f / DD);
    float var = tot2 * (1.f / DD) - mu * mu;
    float rstd = rsqrtf(var + LN_EPS);
    y[i] = (v - mu) * rstd * g[t] + b[t];
}

// NT GEMM (unchanged from R10: FFMA2 k-packed, 8x8 micro-tile, 64x128 block).
#define GS 18
__global__ void __launch_bounds__(128, 2) gemm_nt(
        const float* __restrict__ A, const float* __restrict__ W,
        const float* __restrict__ bias, const float* __restrict__ res,
        float* __restrict__ C, int epi) {
    __shared__ float As[64 * GS];
    __shared__ float Bs[128 * GS];
    int tid = threadIdx.x;
    int bm = blockIdx.y * 64, bn = blockIdx.x * 128;
    int tr = (tid >> 4) * 8;
    int tc = tid & 15;

    int am[2], ak[2], wn[4], wk[4];
    #pragma unroll
    for (int p = 0; p < 2; p++) { int idx = tid + p * 128; am[p] = idx >> 2; ak[p] = (idx & 3) * 4; }
    #pragma unroll
    for (int p = 0; p < 4; p++) { int idx = tid + p * 128; wn[p] = idx >> 2; wk[p] = (idx & 3) * 4; }

    ull acc2[8][8];
    #pragma unroll
    for (int i = 0; i < 8; i++)
        #pragma unroll
        for (int j = 0; j < 8; j++) acc2[i][j] = 0ull;

    float4 pa[2], pb[4];
    #pragma unroll
    for (int p = 0; p < 2; p++) pa[p] = *(const float4*)&A[(size_t)(bm + am[p]) * DD + ak[p]];
    #pragma unroll
    for (int p = 0; p < 4; p++) pb[p] = *(const float4*)&W[(size_t)(bn + wn[p]) * DD + wk[p]];

    for (int k0 = 0; k0 < DD; k0 += 16) {
        #pragma unroll
        for (int p = 0; p < 2; p++) {
            As[am[p] * GS + ak[p] + 0] = pa[p].x; As[am[p] * GS + ak[p] + 1] = pa[p].y;
            As[am[p] * GS + ak[p] + 2] = pa[p].z; As[am[p] * GS + ak[p] + 3] = pa[p].w;
        }
        #pragma unroll
        for (int p = 0; p < 4; p++) {
            Bs[wn[p] * GS + wk[p] + 0] = pb[p].x; Bs[wn[p] * GS + wk[p] + 1] = pb[p].y;
            Bs[wn[p] * GS + wk[p] + 2] = pb[p].z; Bs[wn[p] * GS + wk[p] + 3] = pb[p].w;
        }
        __syncthreads();

        if (k0 + 16 < DD) {
            #pragma unroll
            for (int p = 0; p < 2; p++) pa[p] = *(const float4*)&A[(size_t)(bm + am[p]) * DD + k0 + 16 + ak[p]];
            #pragma unroll
            for (int p = 0; p < 4; p++) pb[p] = *(const float4*)&W[(size_t)(bn + wn[p]) * DD + k0 + 16 + wk[p]];
        }

        #pragma unroll
        for (int kk = 0; kk < 16; kk += 2) {
            ull a2[8], b2[8];
            #pragma unroll
            for (int i = 0; i < 8; i++) a2[i] = *(const ull*)&As[(tr + i) * GS + kk];
            #pragma unroll
            for (int j = 0; j < 8; j++) b2[j] = *(const ull*)&Bs[(tc + 16 * j) * GS + kk];
            #pragma unroll
            for (int i = 0; i < 8; i++)
                #pragma unroll
                for (int j = 0; j < 8; j++) acc2[i][j] = ffma2(a2[i], b2[j], acc2[i][j]);
        }
        __syncthreads();
    }

    #pragma unroll
    for (int i = 0; i < 8; i++) {
        int m = bm + tr + i;
        #pragma unroll
        for (int j = 0; j < 8; j++) {
            int n = bn + tc + 16 * j;
            float v = hsum2(acc2[i][j]);
            if (epi >= 1) v += bias[n];
            if (epi == 1) v = fmaxf(v, 0.f);
            if (epi == 2) v += res[(size_t)m * DD + n];
            C[(size_t)m * DD + n] = v;
        }
    }
}

// ---------------------------------------------------------------------------
// Flash attention via mma.sync bf16 hi/lo split.
// 128-row q-tile, 128-col kv-tiles, 8 warps; warp w owns rows w*16..w*16+15.
// S = Q@K^T (3 MMAs per product for hi/lo), softmax in C-fragment registers,
// P stays in registers as the A-fragment of P@V (no smem round-trip).
// Tiles in smem as bf16 hi/lo, row stride RS=72 bf16 (144B: conflict-free LDSM).
#define RS 72
#define T_QH 0
#define T_QL (128*RS)
#define T_KH (2*128*RS)
#define T_KL (3*128*RS)
#define T_VH (4*128*RS)
#define T_VL (5*128*RS)
#define SMEM_ATTN (6*128*RS*2)   // 110592 B
__global__ void __launch_bounds__(256, 1) attn_kernel(
        const float* __restrict__ q, const float* __restrict__ k,
        const float* __restrict__ v, float* __restrict__ att) {
    extern __shared__ unsigned short sm16[];
    uint32_t base = smem_u32(sm16);

    int bh = blockIdx.y;
    int b = bh >> 2, h = bh & 3;
    int qt = 31 - blockIdx.x;           // longest first
    int tid = threadIdx.x;
    int w = tid >> 5, lane = tid & 31;
    int lr = lane & 7, grp = lane >> 3;
    int m0 = w * 16;

    const float* qbase = q + (size_t)b * SS * DD + h * HD;
    const float* kbase = k + (size_t)b * SS * DD + h * HD;
    const float* vbase = v + (size_t)b * SS * DD + h * HD;

    // Q tile -> bf16 hi/lo (scaled by 1/TEMP = 0.125)
    #pragma unroll
    for (int it = 0; it < 8; it++) {
        int l = tid + it * 256;
        int rr = l >> 4, d4 = (l & 15) * 4;
        float4 tv = *(const float4*)&qbase[(size_t)(qt * 128 + rr) * DD + d4];
        uint32_t h01, l01, h23, l23;
        split2(tv.x * 0.125f, tv.y * 0.125f, h01, l01);
        split2(tv.z * 0.125f, tv.w * 0.125f, h23, l23);
        *(uint2*)&sm16[T_QH + rr * RS + d4] = make_uint2(h01, h23);
        *(uint2*)&sm16[T_QL + rr * RS + d4] = make_uint2(l01, l23);
    }

    float oacc[8][4];
    #pragma unroll
    for (int d = 0; d < 8; d++)
        #pragma unroll
        for (int e = 0; e < 4; e++) oacc[d][e] = 0.f;
    float mA = -INFINITY, mB = -INFINITY, lA = 0.f, lB = 0.f;

    // ldmatrix lane-address components (constant per thread)
    int a_row = ((grp & 1) ? 8 : 0) + lr;   // A frag (Q): + m0, col kc*16 + ((grp&2)?8:0)
    int a_cof = (grp & 2) ? 8 : 0;
    int b_row = ((grp & 2) ? 8 : 0) + lr;   // B frag (K): + n0, col kc*16 + ((grp&1)?8:0)
    int b_cof = (grp & 1) ? 8 : 0;
    int v_row = ((grp & 1) ? 8 : 0) + lr;   // B frag (V, trans): + j0, col dp*16 + ((grp&2)?8:0)
    int v_cof = (grp & 2) ? 8 : 0;

    for (int kt = 0; kt <= qt; kt++) {
        // stage K,V tile -> bf16 hi/lo
        #pragma unroll
        for (int it = 0; it < 8; it++) {
            int l = tid + it * 256;
            int rr = l >> 4, d4 = (l & 15) * 4;
            size_t gidx = (size_t)(kt * 128 + rr) * DD + d4;
            float4 kv = *(const float4*)&kbase[gidx];
            float4 vv = *(const float4*)&vbase[gidx];
            uint32_t h01, l01, h23, l23;
            split2(kv.x, kv.y, h01, l01); split2(kv.z, kv.w, h23, l23);
            *(uint2*)&sm16[T_KH + rr * RS + d4] = make_uint2(h01, h23);
            *(uint2*)&sm16[T_KL + rr * RS + d4] = make_uint2(l01, l23);
            split2(vv.x, vv.y, h01, l01); split2(vv.z, vv.w, h23, l23);
            *(uint2*)&sm16[T_VH + rr * RS + d4] = make_uint2(h01, h23);
            *(uint2*)&sm16[T_VL + rr * RS + d4] = make_uint2(l01, l23);
        }
        __syncthreads();

        // ---- S = Q @ K^T  (16 x 128 per warp), hi/lo split ----
        float sacc[16][4];
        #pragma unroll
        for (int nb = 0; nb < 16; nb++)
            #pragma unroll
            for (int e = 0; e < 4; e++) sacc[nb][e] = 0.f;

        #pragma unroll
        for (int kc = 0; kc < 4; kc++) {
            uint32_t Ah[4], Al[4];
            uint32_t qoff = ((m0 + a_row) * RS + kc * 16 + a_cof) * 2;
            ldmx4(Ah, base + T_QH * 2 + qoff);
            ldmx4(Al, base + T_QL * 2 + qoff);
            #pragma unroll
            for (int np = 0; np < 8; np++) {
                uint32_t Bh[4], Bl[4];
                uint32_t koff = ((np * 16 + b_row) * RS + kc * 16 + b_cof) * 2;
                ldmx4(Bh, base + T_KH * 2 + koff);
                ldmx4(Bl, base + T_KL * 2 + koff);
                mma_bf16(sacc[2 * np],     Ah, Bh);
                mma_bf16(sacc[2 * np + 1], Ah, Bh + 2);
                mma_bf16(sacc[2 * np],     Ah, Bl);
                mma_bf16(sacc[2 * np + 1], Ah, Bl + 2);
                mma_bf16(sacc[2 * np],     Al, Bh);
                mma_bf16(sacc[2 * np + 1], Al, Bh + 2);
            }
        }

        // ---- softmax (C-fragment layout: rows m0+lane/4, m0+lane/4+8) ----
        int rAl = m0 + (lane >> 2);       // local row (0..127)
        int cb = (lane & 3) * 2;
        if (kt == qt) {
            #pragma unroll
            for (int nb = 0; nb < 16; nb++) {
                int colL = nb * 8 + cb;
                if (colL     > rAl)     sacc[nb][0] = -INFINITY;
                if (colL + 1 > rAl)     sacc[nb][1] = -INFINITY;
                if (colL     > rAl + 8) sacc[nb][2] = -INFINITY;
                if (colL + 1 > rAl + 8) sacc[nb][3] = -INFINITY;
            }
        }
        float mxA = -INFINITY, mxB = -INFINITY;
        #pragma unroll
        for (int nb = 0; nb < 16; nb++) {
            mxA = fmaxf(mxA, fmaxf(sacc[nb][0], sacc[nb][1]));
            mxB = fmaxf(mxB, fmaxf(sacc[nb][2], sacc[nb][3]));
        }
        mxA = fmaxf(mxA, __shfl_xor_sync(0xffffffffu, mxA, 1));
        mxA = fmaxf(mxA, __shfl_xor_sync(0xffffffffu, mxA, 2));
        mxB = fmaxf(mxB, __shfl_xor_sync(0xffffffffu, mxB, 1));
        mxB = fmaxf(mxB, __shfl_xor_sync(0xffffffffu, mxB, 2));
        float mnA = fmaxf(mA, mxA), mnB = fmaxf(mB, mxB);
        float alA = __expf(mA - mnA), alB = __expf(mB - mnB);
        mA = mnA; mB = mnB;

        float lsA = 0.f, lsB = 0.f;
        #pragma unroll
        for (int nb = 0; nb < 16; nb++) {
            sacc[nb][0] = __expf(sacc[nb][0] - mnA); lsA += sacc[nb][0];
            sacc[nb][1] = __expf(sacc[nb][1] - mnA); lsA += sacc[nb][1];
            sacc[nb][2] = __expf(sacc[nb][2] - mnB); lsB += sacc[nb][2];
            sacc[nb][3] = __expf(sacc[nb][3] - mnB); lsB += sacc[nb][3];
        }
        lsA += __shfl_xor_sync(0xffffffffu, lsA, 1);
        lsA += __shfl_xor_sync(0xffffffffu, lsA, 2);
        lsB += __shfl_xor_sync(0xffffffffu, lsB, 1);
        lsB += __shfl_xor_sync(0xffffffffu, lsB, 2);
        lA = lA * alA + lsA;
        lB = lB * alB + lsB;
        #pragma unroll
        for (int d = 0; d < 8; d++) {
            oacc[d][0] *= alA; oacc[d][1] *= alA;
            oacc[d][2] *= alB; oacc[d][3] *= alB;
        }

        // ---- pack P into A-fragments (hi/lo), registers only ----
        uint32_t ph[8][4], pl[8][4];
        #pragma unroll
        for (int jc = 0; jc < 8; jc++) {
            split2(sacc[2 * jc][0],     sacc[2 * jc][1],     ph[jc][0], pl[jc][0]);
            split2(sacc[2 * jc][2],     sacc[2 * jc][3],     ph[jc][1], pl[jc][1]);
            split2(sacc[2 * jc + 1][0], sacc[2 * jc + 1][1], ph[jc][2], pl[jc][2]);
            split2(sacc[2 * jc + 1][2], sacc[2 * jc + 1][3], ph[jc][3], pl[jc][3]);
        }

        // ---- O += P @ V ----
        #pragma unroll
        for (int jc = 0; jc < 8; jc++) {
            #pragma unroll
            for (int dp = 0; dp < 4; dp++) {
                uint32_t Bvh[4], Bvl[4];
                uint32_t voff = ((jc * 16 + v_row) * RS + dp * 16 + v_cof) * 2;
                ldmx4t(Bvh, base + T_VH * 2 + voff);
                ldmx4t(Bvl, base + T_VL * 2 + voff);
                mma_bf16(oacc[2 * dp],     ph[jc], Bvh);
                mma_bf16(oacc[2 * dp + 1], ph[jc], Bvh + 2);
                mma_bf16(oacc[2 * dp],     ph[jc], Bvl);
                mma_bf16(oacc[2 * dp + 1], ph[jc], Bvl + 2);
                mma_bf16(oacc[2 * dp],     pl[jc], Bvh);
                mma_bf16(oacc[2 * dp + 1], pl[jc], Bvh + 2);
            }
        }
        __syncthreads();
    }

    float invA = 1.f / lA, invB = 1.f / lB;
    float* obase = att + (size_t)b * SS * DD + h * HD;
    int rgA = qt * 128 + m0 + (lane >> 2);
    int cb = (lane & 3) * 2;
    #pragma unroll
    for (int d = 0; d < 8; d++) {
        int col = d * 8 + cb;
        *(float2*)&obase[(size_t)rgA * DD + col] =
            make_float2(oacc[d][0] * invA, oacc[d][1] * invA);
        *(float2*)&obase[(size_t)(rgA + 8) * DD + col] =
            make_float2(oacc[d][2] * invB, oacc[d][3] * invB);
    }
}

extern "C" void kernel_launch(void* const* d_in, const int* in_sizes, int n_in,
                              void* d_out, int out_size) {
    const float* x   = (const float*)d_in[0];
    const float* Wq  = (const float*)d_in[1];
    const float* Wk  = (const float*)d_in[2];
    const float* Wv  = (const float*)d_in[3];
    const float* g1  = (const float*)d_in[4];
    const float* b1  = (const float*)d_in[5];
    const float* g2  = (const float*)d_in[6];
    const float* b2  = (const float*)d_in[7];
    const float* W1  = (const float*)d_in[8];
    const float* bf1 = (const float*)d_in[9];
    const float* W2  = (const float*)d_in[10];
    const float* bf2 = (const float*)d_in[11];
    float* out = (float*)d_out;

    float *xn, *q, *k, *v, *att, *xt, *h, *a1;
    cudaGetSymbolAddress((void**)&xn,  g_xn);
    cudaGetSymbolAddress((void**)&q,   g_q);
    cudaGetSymbolAddress((void**)&k,   g_k);
    cudaGetSymbolAddress((void**)&v,   g_v);
    cudaGetSymbolAddress((void**)&att, g_att);
    cudaGetSymbolAddress((void**)&xt,  g_xt);
    cudaGetSymbolAddress((void**)&h,   g_h);
    cudaGetSymbolAddress((void**)&a1,  g_a1);

    cudaFuncSetAttribute(attn_kernel, cudaFuncAttributeMaxDynamicSharedMemorySize, SMEM_ATTN);

    dim3 ggrid(DD / 128, NN / 64);   // (2, 256), 128 threads

    // 1. xn = LN(x)
    ln_kernel<<<NN, 256>>>(x, nullptr, g1, b1, nullptr, xn);
    // 2. QKV projections
    gemm_nt<<<ggrid, 128>>>(xn, Wq, nullptr, nullptr, q, 0);
    gemm_nt<<<ggrid, 128>>>(xn, Wk, nullptr, nullptr, k, 0);
    gemm_nt<<<ggrid, 128>>>(xn, Wv, nullptr, nullptr, v, 0);
    // 3. causal flash attention (mma.sync bf16 hi/lo)
    attn_kernel<<<dim3(SS / 128, BB * HH), 256, SMEM_ATTN>>>(q, k, v, att);
    // 4. xt = x + att; h = LN(xt)
    ln_kernel<<<NN, 256>>>(x, att, g2, b2, xt, h);
    // 5. a1 = relu(h @ W1^T + bf1)
    gemm_nt<<<ggrid, 128>>>(h, W1, bf1, nullptr, a1, 1);
    // 6. out = xt + a1 @ W2^T + bf2
    gemm_nt<<<ggrid, 128>>>(a1, W2, bf2, xt, out, 2);
}

// round 12
// speedup vs baseline: 2.7705x; 1.3389x over previous
#include <cuda_runtime.h>
#include <cuda_bf16.h>
#include <math.h>
#include <stdint.h>

#define BB 4
#define SS 4096
#define DD 256
#define HH 4
#define HD 64
#define NN (BB*SS)
#define LN_EPS 1e-5f

typedef unsigned long long ull;

// Scratch (allocation-free): 8 x 16 MiB device globals.
__device__ float g_xn[NN*DD];
__device__ float g_q[NN*DD];
__device__ float g_k[NN*DD];
__device__ float g_v[NN*DD];
__device__ float g_att[NN*DD];
__device__ float g_xt[NN*DD];
__device__ float g_h[NN*DD];
__device__ float g_a1[NN*DD];

__device__ __forceinline__ uint32_t smem_u32(const void* p) {
    uint32_t a;
    asm("{ .reg .u64 t; cvta.to.shared.u64 t, %1; cvt.u32.u64 %0, t; }" : "=r"(a) : "l"(p));
    return a;
}

// ---- mma.sync / ldmatrix (base sm_80 ISA, valid on compute_103) ----
__device__ __forceinline__ void ldmx4(uint32_t* r, uint32_t a) {
    asm volatile("ldmatrix.sync.aligned.m8n8.x4.shared.b16 {%0,%1,%2,%3}, [%4];"
        : "=r"(r[0]), "=r"(r[1]), "=r"(r[2]), "=r"(r[3]) : "r"(a));
}
__device__ __forceinline__ void ldmx4t(uint32_t* r, uint32_t a) {
    asm volatile("ldmatrix.sync.aligned.m8n8.x4.trans.shared.b16 {%0,%1,%2,%3}, [%4];"
        : "=r"(r[0]), "=r"(r[1]), "=r"(r[2]), "=r"(r[3]) : "r"(a));
}
__device__ __forceinline__ void mma_bf16(float* c, const uint32_t* a, const uint32_t* b) {
    asm volatile("mma.sync.aligned.m16n8k16.row.col.f32.bf16.bf16.f32 "
        "{%0,%1,%2,%3}, {%4,%5,%6,%7}, {%8,%9}, {%0,%1,%2,%3};"
        : "+f"(c[0]), "+f"(c[1]), "+f"(c[2]), "+f"(c[3])
        : "r"(a[0]), "r"(a[1]), "r"(a[2]), "r"(a[3]), "r"(b[0]), "r"(b[1]));
}

// hi/lo bf16 split of an fp32 pair (packed bf16x2: e0 in low half).
__device__ __forceinline__ void split2(float e0, float e1, uint32_t& h, uint32_t& l) {
    __nv_bfloat162 hb = __floats2bfloat162_rn(e0, e1);
    h = reinterpret_cast<uint32_t&>(hb);
    float f0 = __bfloat162float(hb.x);
    float f1 = __bfloat162float(hb.y);
    __nv_bfloat162 lb = __floats2bfloat162_rn(e0 - f0, e1 - f1);
    l = reinterpret_cast<uint32_t&>(lb);
}

__device__ __forceinline__ float warp_sum(float v) {
    #pragma unroll
    for (int o = 16; o; o >>= 1) v += __shfl_xor_sync(0xffffffffu, v, o);
    return v;
}

// LayerNorm (optionally fused residual add). One block per row, 256 threads.
__global__ void ln_kernel(const float* __restrict__ x, const float* __restrict__ res,
                          const float* __restrict__ g, const float* __restrict__ b,
                          float* __restrict__ xt_out, float* __restrict__ y) {
    int row = blockIdx.x;
    int t = threadIdx.x;
    size_t i = (size_t)row * DD + t;
    float v = x[i];
    if (res) v += res[i];
    if (xt_out) xt_out[i] = v;

    __shared__ float red1[8], red2[8];
    float s1 = warp_sum(v);
    float s2 = warp_sum(v * v);
    if ((t & 31) == 0) { red1[t >> 5] = s1; red2[t >> 5] = s2; }
    __syncthreads();
    float tot = 0.f, tot2 = 0.f;
    #pragma unroll
    for (int w = 0; w < 8; w++) { tot += red1[w]; tot2 += red2[w]; }
    float mu = tot * (1.f / DD);
    float var = tot2 * (1.f / DD) - mu * mu;
    float rstd = rsqrtf(var + LN_EPS);
    y[i] = (v - mu) * rstd * g[t] + b[t];
}

// ---------------------------------------------------------------------------
// NT GEMM via mma.sync bf16 hi/lo: C[M,256] = A @ W^T (+epi).
// CTA tile 128x128, K staged in 64-wide chunks as bf16 hi/lo (smem 72KB).
// 8 warps in a 4(M)x2(N) grid: warp tile 32x64 -> 12 ldmatrix per 48 MMAs.
// Register-prefetch of next chunk's fp32. epi: 0 plain; 1 +bias,relu; 2 +bias+res.
#define GRS 72
#define G_AH 0
#define G_AL (128*GRS)
#define G_BH (2*128*GRS)
#define G_BL (3*128*GRS)
#define SMEM_GEMM (4*128*GRS*2)   // 73728 B
__global__ void __launch_bounds__(256) gemm_tc(
        const float* __restrict__ A, const float* __restrict__ W,
        const float* __restrict__ bias, const float* __restrict__ res,
        float* __restrict__ C, int epi) {
    extern __shared__ unsigned short gsm[];
    uint32_t base = smem_u32(gsm);

    int tid = threadIdx.x;
    int w = tid >> 5, lane = tid & 31;
    int lr = lane & 7, grp = lane >> 3;
    int wm = w >> 1, wn = w & 1;          // warp tile: rows wm*32, cols wn*64
    int bm = blockIdx.y * 128, bn = blockIdx.x * 128;

    // ldmatrix lane-address components
    int a_row = ((grp & 1) ? 8 : 0) + lr;
    int a_cof = (grp & 2) ? 8 : 0;
    int b_row = ((grp & 2) ? 8 : 0) + lr;
    int b_cof = (grp & 1) ? 8 : 0;

    // staging indices: l = tid + it*256 -> rr = l>>4 (row 0..127), d4 = (l&15)*4
    float cacc[2][8][4];
    #pragma unroll
    for (int am = 0; am < 2; am++)
        #pragma unroll
        for (int nb = 0; nb < 8; nb++)
            #pragma unroll
            for (int e = 0; e < 4; e++) cacc[am][nb][e] = 0.f;

    float4 pa[8], pw[8];
    #pragma unroll
    for (int it = 0; it < 8; it++) {
        int l = tid + it * 256;
        int rr = l >> 4, d4 = (l & 15) * 4;
        pa[it] = *(const float4*)&A[(size_t)(bm + rr) * DD + d4];
        pw[it] = *(const float4*)&W[(size_t)(bn + rr) * DD + d4];
    }

    for (int c = 0; c < 4; c++) {
        // stage chunk c (already in regs) as bf16 hi/lo
        #pragma unroll
        for (int it = 0; it < 8; it++) {
            int l = tid + it * 256;
            int rr = l >> 4, d4 = (l & 15) * 4;
            uint32_t h01, l01, h23, l23;
            split2(pa[it].x, pa[it].y, h01, l01);
            split2(pa[it].z, pa[it].w, h23, l23);
            *(uint2*)&gsm[G_AH + rr * GRS + d4] = make_uint2(h01, h23);
            *(uint2*)&gsm[G_AL + rr * GRS + d4] = make_uint2(l01, l23);
            split2(pw[it].x, pw[it].y, h01, l01);
            split2(pw[it].z, pw[it].w, h23, l23);
            *(uint2*)&gsm[G_BH + rr * GRS + d4] = make_uint2(h01, h23);
            *(uint2*)&gsm[G_BL + rr * GRS + d4] = make_uint2(l01, l23);
        }
        __syncthreads();

        if (c < 3) {   // prefetch next chunk
            #pragma unroll
            for (int it = 0; it < 8; it++) {
                int l = tid + it * 256;
                int rr = l >> 4, d4 = (c + 1) * 64 + (l & 15) * 4;
                pa[it] = *(const float4*)&A[(size_t)(bm + rr) * DD + d4];
                pw[it] = *(const float4*)&W[(size_t)(bn + rr) * DD + d4];
            }
        }

        #pragma unroll
        for (int kc = 0; kc < 4; kc++) {
            uint32_t Ah[2][4], Al[2][4];
            #pragma unroll
            for (int am = 0; am < 2; am++) {
                uint32_t aoff = ((wm * 32 + am * 16 + a_row) * GRS + kc * 16 + a_cof) * 2;
                ldmx4(Ah[am], base + G_AH * 2 + aoff);
                ldmx4(Al[am], base + G_AL * 2 + aoff);
            }
            #pragma unroll
            for (int np = 0; np < 4; np++) {
                uint32_t Bh[4], Bl[4];
                uint32_t boff = ((wn * 64 + np * 16 + b_row) * GRS + kc * 16 + b_cof) * 2;
                ldmx4(Bh, base + G_BH * 2 + boff);
                ldmx4(Bl, base + G_BL * 2 + boff);
                #pragma unroll
                for (int am = 0; am < 2; am++) {
                    mma_bf16(cacc[am][2 * np],     Ah[am], Bh);
                    mma_bf16(cacc[am][2 * np + 1], Ah[am], Bh + 2);
                    mma_bf16(cacc[am][2 * np],     Ah[am], Bl);
                    mma_bf16(cacc[am][2 * np + 1], Ah[am], Bl + 2);
                    mma_bf16(cacc[am][2 * np],     Al[am], Bh);
                    mma_bf16(cacc[am][2 * np + 1], Al[am], Bh + 2);
                }
            }
        }
        __syncthreads();
    }

    // Epilogue from C-fragment layout.
    int cb = (lane & 3) * 2;
    #pragma unroll
    for (int am = 0; am < 2; am++) {
        int r0 = bm + wm * 32 + am * 16 + (lane >> 2);
        #pragma unroll
        for (int nb = 0; nb < 8; nb++) {
            int col = bn + wn * 64 + nb * 8 + cb;
            #pragma unroll
            for (int half = 0; half < 2; half++) {
                int r = r0 + half * 8;
                float v0 = cacc[am][nb][2 * half];
                float v1 = cacc[am][nb][2 * half + 1];
                if (epi >= 1) { v0 += bias[col]; v1 += bias[col + 1]; }
                if (epi == 1) { v0 = fmaxf(v0, 0.f); v1 = fmaxf(v1, 0.f); }
                if (epi == 2) {
                    float2 rv = *(const float2*)&res[(size_t)r * DD + col];
                    v0 += rv.x; v1 += rv.y;
                }
                *(float2*)&C[(size_t)r * DD + col] = make_float2(v0, v1);
            }
        }
    }
}

// ---------------------------------------------------------------------------
// Flash attention via mma.sync bf16 hi/lo split (unchanged from R11).
#define RS 72
#define T_QH 0
#define T_QL (128*RS)
#define T_KH (2*128*RS)
#define T_KL (3*128*RS)
#define T_VH (4*128*RS)
#define T_VL (5*128*RS)
#define SMEM_ATTN (6*128*RS*2)   // 110592 B
__global__ void __launch_bounds__(256, 1) attn_kernel(
        const float* __restrict__ q, const float* __restrict__ k,
        const float* __restrict__ v, float* __restrict__ att) {
    extern __shared__ unsigned short sm16[];
    uint32_t base = smem_u32(sm16);

    int bh = blockIdx.y;
    int b = bh >> 2, h = bh & 3;
    int qt = 31 - blockIdx.x;           // longest first
    int tid = threadIdx.x;
    int w = tid >> 5, lane = tid & 31;
    int lr = lane & 7, grp = lane >> 3;
    int m0 = w * 16;

    const float* qbase = q + (size_t)b * SS * DD + h * HD;
    const float* kbase = k + (size_t)b * SS * DD + h * HD;
    const float* vbase = v + (size_t)b * SS * DD + h * HD;

    #pragma unroll
    for (int it = 0; it < 8; it++) {
        int l = tid + it * 256;
        int rr = l >> 4, d4 = (l & 15) * 4;
        float4 tv = *(const float4*)&qbase[(size_t)(qt * 128 + rr) * DD + d4];
        uint32_t h01, l01, h23, l23;
        split2(tv.x * 0.125f, tv.y * 0.125f, h01, l01);
        split2(tv.z * 0.125f, tv.w * 0.125f, h23, l23);
        *(uint2*)&sm16[T_QH + rr * RS + d4] = make_uint2(h01, h23);
        *(uint2*)&sm16[T_QL + rr * RS + d4] = make_uint2(l01, l23);
    }

    float oacc[8][4];
    #pragma unroll
    for (int d = 0; d < 8; d++)
        #pragma unroll
        for (int e = 0; e < 4; e++) oacc[d][e] = 0.f;
    float mA = -INFINITY, mB = -INFINITY, lA = 0.f, lB = 0.f;

    int a_row = ((grp & 1) ? 8 : 0) + lr;
    int a_cof = (grp & 2) ? 8 : 0;
    int b_row = ((grp & 2) ? 8 : 0) + lr;
    int b_cof = (grp & 1) ? 8 : 0;
    int v_row = ((grp & 1) ? 8 : 0) + lr;
    int v_cof = (grp & 2) ? 8 : 0;

    for (int kt = 0; kt <= qt; kt++) {
        #pragma unroll
        for (int it = 0; it < 8; it++) {
            int l = tid + it * 256;
            int rr = l >> 4, d4 = (l & 15) * 4;
            size_t gidx = (size_t)(kt * 128 + rr) * DD + d4;
            float4 kv = *(const float4*)&kbase[gidx];
            float4 vv = *(const float4*)&vbase[gidx];
            uint32_t h01, l01, h23, l23;
            split2(kv.x, kv.y, h01, l01); split2(kv.z, kv.w, h23, l23);
            *(uint2*)&sm16[T_KH + rr * RS + d4] = make_uint2(h01, h23);
            *(uint2*)&sm16[T_KL + rr * RS + d4] = make_uint2(l01, l23);
            split2(vv.x, vv.y, h01, l01); split2(vv.z, vv.w, h23, l23);
            *(uint2*)&sm16[T_VH + rr * RS + d4] = make_uint2(h01, h23);
            *(uint2*)&sm16[T_VL + rr * RS + d4] = make_uint2(l01, l23);
        }
        __syncthreads();

        float sacc[16][4];
        #pragma unroll
        for (int nb = 0; nb < 16; nb++)
            #pragma unroll
            for (int e = 0; e < 4; e++) sacc[nb][e] = 0.f;

        #pragma unroll
        for (int kc = 0; kc < 4; kc++) {
            uint32_t Ah[4], Al[4];
            uint32_t qoff = ((m0 + a_row) * RS + kc * 16 + a_cof) * 2;
            ldmx4(Ah, base + T_QH * 2 + qoff);
            ldmx4(Al, base + T_QL * 2 + qoff);
            #pragma unroll
            for (int np = 0; np < 8; np++) {
                uint32_t Bh[4], Bl[4];
                uint32_t koff = ((np * 16 + b_row) * RS + kc * 16 + b_cof) * 2;
                ldmx4(Bh, base + T_KH * 2 + koff);
                ldmx4(Bl, base + T_KL * 2 + koff);
                mma_bf16(sacc[2 * np],     Ah, Bh);
                mma_bf16(sacc[2 * np + 1], Ah, Bh + 2);
                mma_bf16(sacc[2 * np],     Ah, Bl);
                mma_bf16(sacc[2 * np + 1], Ah, Bl + 2);
                mma_bf16(sacc[2 * np],     Al, Bh);
                mma_bf16(sacc[2 * np + 1], Al, Bh + 2);
            }
        }

        int rAl = m0 + (lane >> 2);
        int cb = (lane & 3) * 2;
        if (kt == qt) {
            #pragma unroll
            for (int nb = 0; nb < 16; nb++) {
                int colL = nb * 8 + cb;
                if (colL     > rAl)     sacc[nb][0] = -INFINITY;
                if (colL + 1 > rAl)     sacc[nb][1] = -INFINITY;
                if (colL     > rAl + 8) sacc[nb][2] = -INFINITY;
                if (colL + 1 > rAl + 8) sacc[nb][3] = -INFINITY;
            }
        }
        float mxA = -INFINITY, mxB = -INFINITY;
        #pragma unroll
        for (int nb = 0; nb < 16; nb++) {
            mxA = fmaxf(mxA, fmaxf(sacc[nb][0], sacc[nb][1]));
            mxB = fmaxf(mxB, fmaxf(sacc[nb][2], sacc[nb][3]));
        }
        mxA = fmaxf(mxA, __shfl_xor_sync(0xffffffffu, mxA, 1));
        mxA = fmaxf(mxA, __shfl_xor_sync(0xffffffffu, mxA, 2));
        mxB = fmaxf(mxB, __shfl_xor_sync(0xffffffffu, mxB, 1));
        mxB = fmaxf(mxB, __shfl_xor_sync(0xffffffffu, mxB, 2));
        float mnA = fmaxf(mA, mxA), mnB = fmaxf(mB, mxB);
        float alA = __expf(mA - mnA), alB = __expf(mB - mnB);
        mA = mnA; mB = mnB;

        float lsA = 0.f, lsB = 0.f;
        #pragma unroll
        for (int nb = 0; nb < 16; nb++) {
            sacc[nb][0] = __expf(sacc[nb][0] - mnA); lsA += sacc[nb][0];
            sacc[nb][1] = __expf(sacc[nb][1] - mnA); lsA += sacc[nb][1];
            sacc[nb][2] = __expf(sacc[nb][2] - mnB); lsB += sacc[nb][2];
            sacc[nb][3] = __expf(sacc[nb][3] - mnB); lsB += sacc[nb][3];
        }
        lsA += __shfl_xor_sync(0xffffffffu, lsA, 1);
        lsA += __shfl_xor_sync(0xffffffffu, lsA, 2);
        lsB += __shfl_xor_sync(0xffffffffu, lsB, 1);
        lsB += __shfl_xor_sync(0xffffffffu, lsB, 2);
        lA = lA * alA + lsA;
        lB = lB * alB + lsB;
        #pragma unroll
        for (int d = 0; d < 8; d++) {
            oacc[d][0] *= alA; oacc[d][1] *= alA;
            oacc[d][2] *= alB; oacc[d][3] *= alB;
        }

        uint32_t ph[8][4], pl[8][4];
        #pragma unroll
        for (int jc = 0; jc < 8; jc++) {
            split2(sacc[2 * jc][0],     sacc[2 * jc][1],     ph[jc][0], pl[jc][0]);
            split2(sacc[2 * jc][2],     sacc[2 * jc][3],     ph[jc][1], pl[jc][1]);
            split2(sacc[2 * jc + 1][0], sacc[2 * jc + 1][1], ph[jc][2], pl[jc][2]);
            split2(sacc[2 * jc + 1][2], sacc[2 * jc + 1][3], ph[jc][3], pl[jc][3]);
        }

        #pragma unroll
        for (int jc = 0; jc < 8; jc++) {
            #pragma unroll
            for (int dp = 0; dp < 4; dp++) {
                uint32_t Bvh[4], Bvl[4];
                uint32_t voff = ((jc * 16 + v_row) * RS + dp * 16 + v_cof) * 2;
                ldmx4t(Bvh, base + T_VH * 2 + voff);
                ldmx4t(Bvl, base + T_VL * 2 + voff);
                mma_bf16(oacc[2 * dp],     ph[jc], Bvh);
                mma_bf16(oacc[2 * dp + 1], ph[jc], Bvh + 2);
                mma_bf16(oacc[2 * dp],     ph[jc], Bvl);
                mma_bf16(oacc[2 * dp + 1], ph[jc], Bvl + 2);
                mma_bf16(oacc[2 * dp],     pl[jc], Bvh);
                mma_bf16(oacc[2 * dp + 1], pl[jc], Bvh + 2);
            }
        }
        __syncthreads();
    }

    float invA = 1.f / lA, invB = 1.f / lB;
    float* obase = att + (size_t)b * SS * DD + h * HD;
    int rgA = qt * 128 + m0 + (lane >> 2);
    int cb = (lane & 3) * 2;
    #pragma unroll
    for (int d = 0; d < 8; d++) {
        int col = d * 8 + cb;
        *(float2*)&obase[(size_t)rgA * DD + col] =
            make_float2(oacc[d][0] * invA, oacc[d][1] * invA);
        *(float2*)&obase[(size_t)(rgA + 8) * DD + col] =
            make_float2(oacc[d][2] * invB, oacc[d][3] * invB);
    }
}

extern "C" void kernel_launch(void* const* d_in, const int* in_sizes, int n_in,
                              void* d_out, int out_size) {
    const float* x   = (const float*)d_in[0];
    const float* Wq  = (const float*)d_in[1];
    const float* Wk  = (const float*)d_in[2];
    const float* Wv  = (const float*)d_in[3];
    const float* g1  = (const float*)d_in[4];
    const float* b1  = (const float*)d_in[5];
    const float* g2  = (const float*)d_in[6];
    const float* b2  = (const float*)d_in[7];
    const float* W1  = (const float*)d_in[8];
    const float* bf1 = (const float*)d_in[9];
    const float* W2  = (const float*)d_in[10];
    const float* bf2 = (const float*)d_in[11];
    float* out = (float*)d_out;

    float *xn, *q, *k, *v, *att, *xt, *h, *a1;
    cudaGetSymbolAddress((void**)&xn,  g_xn);
    cudaGetSymbolAddress((void**)&q,   g_q);
    cudaGetSymbolAddress((void**)&k,   g_k);
    cudaGetSymbolAddress((void**)&v,   g_v);
    cudaGetSymbolAddress((void**)&att, g_att);
    cudaGetSymbolAddress((void**)&xt,  g_xt);
    cudaGetSymbolAddress((void**)&h,   g_h);
    cudaGetSymbolAddress((void**)&a1,  g_a1);

    cudaFuncSetAttribute(attn_kernel, cudaFuncAttributeMaxDynamicSharedMemorySize, SMEM_ATTN);
    cudaFuncSetAttribute(gemm_tc, cudaFuncAttributeMaxDynamicSharedMemorySize, SMEM_GEMM);

    dim3 ggrid(DD / 128, NN / 128);   // (2, 128)

    // 1. xn = LN(x)
    ln_kernel<<<NN, 256>>>(x, nullptr, g1, b1, nullptr, xn);
    // 2. QKV projections (mma.sync bf16 hi/lo)
    gemm_tc<<<ggrid, 256, SMEM_GEMM>>>(xn, Wq, nullptr, nullptr, q, 0);
    gemm_tc<<<ggrid, 256, SMEM_GEMM>>>(xn, Wk, nullptr, nullptr, k, 0);
    gemm_tc<<<ggrid, 256, SMEM_GEMM>>>(xn, Wv, nullptr, nullptr, v, 0);
    // 3. causal flash attention (mma.sync bf16 hi/lo)
    attn_kernel<<<dim3(SS / 128, BB * HH), 256, SMEM_ATTN>>>(q, k, v, att);
    // 4. xt = x + att; h = LN(xt)
    ln_kernel<<<NN, 256>>>(x, att, g2, b2, xt, h);
    // 5. a1 = relu(h @ W1^T + bf1)
    gemm_tc<<<ggrid, 256, SMEM_GEMM>>>(h, W1, bf1, nullptr, a1, 1);
    // 6. out = xt + a1 @ W2^T + bf2
    gemm_tc<<<ggrid, 256, SMEM_GEMM>>>(a1, W2, bf2, xt, out, 2);
}